// round 17
// baseline (speedup 1.0000x reference)
#include <cuda_runtime.h>

// Problem constants (fixed shapes from reference)
#define BB    2
#define NN    16384
#define MM    4096
#define CC    64
#define KK    16
#define TILE  1024            // points per pipeline stage
#define NTILE (NN / TILE)     // 16 stages
#define WPB   4               // warps per block (each warp = 2 queries)
#define TPB   128
#define NQ    (BB * MM)       // 8192 queries
#define NP    (NQ / 2)        // 4096 query pairs

#define BIGF 1e30f
#define FULLMASK 0xffffffffu

// Scratch (__device__ globals; no allocs allowed)
__device__ float  g_xt[BB * NN * CC];   // transposed features (B,N,C), 8 MB
__device__ float4 g_pts[BB * NN];       // packed points (x,y,z,|p|^2)

// ---------------------------------------------------------------------------
// Prep kernel: fuses point packing and feature transpose.
//   blocks [0, 128)          : pack p1 (B,N,3) -> g_pts (x,y,z,|p|^2)
//   blocks [128, 128+2048)   : transpose x1 (B,C,N) -> g_xt (B,N,C)
// ---------------------------------------------------------------------------
__global__ __launch_bounds__(256) void prep_kernel(const float* __restrict__ p1,
                                                   const float* __restrict__ x1) {
    if (blockIdx.x < 128) {
        const int i = blockIdx.x * 256 + threadIdx.x;  // 0 .. BB*NN-1
        const float x = p1[i * 3 + 0];
        const float y = p1[i * 3 + 1];
        const float z = p1[i * 3 + 2];
        g_pts[i] = make_float4(x, y, z, fmaf(x, x, fmaf(y, y, z * z)));
        return;
    }
    __shared__ float t[32][33];
    const int blk = blockIdx.x - 128;          // 0..2047
    const int b   = blk >> 10;                 // 1024 blocks per batch
    const int r   = blk & 1023;                // 512 x-tiles x 2 c-tiles
    const int n0  = (r & 511) * 32;
    const int c0  = (r >> 9) * 32;
    const int tx  = threadIdx.x & 31;
    const int ty  = threadIdx.x >> 5;          // 0..7

    const float* src = x1  + (size_t)b * CC * NN;
    float*       dst = g_xt + (size_t)b * NN * CC;

#pragma unroll
    for (int i = 0; i < 32; i += 8)
        t[ty + i][tx] = src[(size_t)(c0 + ty + i) * NN + (n0 + tx)];
    __syncthreads();
#pragma unroll
    for (int i = 0; i < 32; i += 8)
        dst[(size_t)(n0 + ty + i) * CC + (c0 + tx)] = t[tx][ty + i];
}

// ---------------------------------------------------------------------------
// KNN: full-scan warp-distributed exact top-16, two queries per warp, fused
// gather/mean. cp.async double-buffered tiles, bitonic warp-sort init,
// single combined gate ballot per 64-point chunk. WPB=4 -> 1024 blocks
// (6.92/SM vs cap 7) for near-perfect single-wave balance.
// Lanes 0..15 hold q0's sorted top-16; lanes 16..31 q1's. Deterministic:
// original point order, no atomics. d' = |p|^2 - 2 q.p (order-equivalent).
// ---------------------------------------------------------------------------
__global__ __launch_bounds__(TPB) void knn_kernel(const float* __restrict__ p2,
                                                  float* __restrict__ out) {
    __shared__ float4 sp[2][TILE];   // 2 x 16 KB

    const int tid  = threadIdx.x;
    const int warp = tid >> 5, lane = tid & 31;
    const int pairId = blockIdx.x * WPB + warp;   // 0..NP-1
    const int b    = pairId >> 11;                // / (MM/2)
    const int m0   = (pairId & 2047) * 2;

    const float* qp = p2 + ((size_t)b * MM + m0) * 3;
    const float n0x = -2.0f * qp[0], n0y = -2.0f * qp[1], n0z = -2.0f * qp[2];
    const float n1x = -2.0f * qp[3], n1y = -2.0f * qp[4], n1z = -2.0f * qp[5];

    const float4* gp = g_pts + (size_t)b * NN;

    // ---- issue first two tile loads (cp.async, 8 x 16B per thread) ----
#define ISSUE_TILE(BUF, T)                                                      \
    {                                                                           \
        const float4* _src = gp + (T) * TILE + tid;                             \
        unsigned _dst = (unsigned)__cvta_generic_to_shared(&sp[(BUF)][tid]);    \
        _Pragma("unroll")                                                       \
        for (int _k = 0; _k < TILE / TPB; _k++)                                 \
            asm volatile("cp.async.cg.shared.global [%0], [%1], 16;"            \
                         :: "r"(_dst + _k * TPB * 16), "l"(_src + _k * TPB));   \
        asm volatile("cp.async.commit_group;");                                 \
    }

    ISSUE_TILE(0, 0)
    ISSUE_TILE(1, 1)

    // ---- init: exact top-16 of points 0..31 via full warp bitonic sort ----
    float topd;                  // sorted lists: q0 lanes 0..15, q1 lanes 16..31
    int   topi;
    {
        const float4 Pi = gp[lane];            // direct LDG (L2), overlaps cp.async
        float s0 = fmaf(n0x, Pi.x, fmaf(n0y, Pi.y, fmaf(n0z, Pi.z, Pi.w)));
        float s1 = fmaf(n1x, Pi.x, fmaf(n1y, Pi.y, fmaf(n1z, Pi.z, Pi.w)));
        int   i0 = lane, i1 = lane;
#pragma unroll
        for (int k = 2; k <= 32; k <<= 1) {
#pragma unroll
            for (int j = k >> 1; j; j >>= 1) {
                {
                    const float od = __shfl_xor_sync(FULLMASK, s0, j);
                    const int   oi = __shfl_xor_sync(FULLMASK, i0, j);
                    const bool keepMin = (((lane & k) == 0) == ((lane & j) == 0));
                    const bool sw = keepMin ? (od < s0) : (od > s0);
                    if (sw) { s0 = od; i0 = oi; }
                }
                {
                    const float od = __shfl_xor_sync(FULLMASK, s1, j);
                    const int   oi = __shfl_xor_sync(FULLMASK, i1, j);
                    const bool keepMin = (((lane & k) == 0) == ((lane & j) == 0));
                    const bool sw = keepMin ? (od < s1) : (od > s1);
                    if (sw) { s1 = od; i1 = oi; }
                }
            }
        }
        const float s1s = __shfl_sync(FULLMASK, s1, (lane + 16) & 31);
        const int   i1s = __shfl_sync(FULLMASK, i1, (lane + 16) & 31);
        topd = (lane < 16) ? s0 : s1s;
        topi = (lane < 16) ? i0 : i1s;
    }
    float tau0 = __shfl_sync(FULLMASK, topd, 15);
    float tau1 = __shfl_sync(FULLMASK, topd, 31);

    auto ins0 = [&](float dc, int ic) {
        const int rank = __popc(__ballot_sync(FULLMASK, topd < dc) & 0xFFFFu);
        const float pd = __shfl_up_sync(FULLMASK, topd, 1);
        const int   pi = __shfl_up_sync(FULLMASK, topi, 1);
        if (lane < 16) {
            if (lane == rank)     { topd = dc; topi = ic; }
            else if (lane > rank) { topd = pd; topi = pi; }
        }
    };
    auto ins1 = [&](float dc, int ic) {
        const int rank = 16 + __popc(__ballot_sync(FULLMASK, topd < dc) >> 16);
        const float pd = __shfl_up_sync(FULLMASK, topd, 1);
        const int   pi = __shfl_up_sync(FULLMASK, topi, 1);
        if (lane >= 16) {
            if (lane == rank)     { topd = dc; topi = ic; }
            else if (lane > rank) { topd = pd; topi = pi; }
        }
    };

#define KNN_CHUNK(BUF, J, BASE)                                                  \
    {                                                                            \
        const float4 Pa = sp[(BUF)][(J) + lane];                                 \
        const float4 Pb = sp[(BUF)][(J) + 32 + lane];                            \
        const float d0a = fmaf(n0x, Pa.x, fmaf(n0y, Pa.y, fmaf(n0z, Pa.z, Pa.w)));\
        const float d0b = fmaf(n0x, Pb.x, fmaf(n0y, Pb.y, fmaf(n0z, Pb.z, Pb.w)));\
        const float d1a = fmaf(n1x, Pa.x, fmaf(n1y, Pa.y, fmaf(n1z, Pa.z, Pa.w)));\
        const float d1b = fmaf(n1x, Pb.x, fmaf(n1y, Pb.y, fmaf(n1z, Pb.z, Pb.w)));\
        const unsigned gate = __ballot_sync(FULLMASK,                            \
            (fminf(d0a, d0b) < tau0) || (fminf(d1a, d1b) < tau1));               \
        if (gate) {                                                              \
            const int ia = (BASE) + (J) + lane;                                  \
            unsigned ba = __ballot_sync(FULLMASK, d0a < tau0);                   \
            unsigned bc = __ballot_sync(FULLMASK, d0b < tau0);                   \
            if (ba | bc) {                                                       \
                while (ba) { const int s2 = __ffs(ba) - 1; ba &= ba - 1;         \
                    ins0(__shfl_sync(FULLMASK, d0a, s2),                         \
                         __shfl_sync(FULLMASK, ia, s2)); }                       \
                while (bc) { const int s2 = __ffs(bc) - 1; bc &= bc - 1;         \
                    ins0(__shfl_sync(FULLMASK, d0b, s2),                         \
                         __shfl_sync(FULLMASK, ia, s2) + 32); }                  \
                tau0 = __shfl_sync(FULLMASK, topd, 15);                          \
            }                                                                    \
            unsigned be = __ballot_sync(FULLMASK, d1a < tau1);                   \
            unsigned bf = __ballot_sync(FULLMASK, d1b < tau1);                   \
            if (be | bf) {                                                       \
                while (be) { const int s2 = __ffs(be) - 1; be &= be - 1;         \
                    ins1(__shfl_sync(FULLMASK, d1a, s2),                         \
                         __shfl_sync(FULLMASK, ia, s2)); }                       \
                while (bf) { const int s2 = __ffs(bf) - 1; bf &= bf - 1;         \
                    ins1(__shfl_sync(FULLMASK, d1b, s2),                         \
                         __shfl_sync(FULLMASK, ia, s2) + 32); }                  \
                tau1 = __shfl_sync(FULLMASK, topd, 31);                          \
            }                                                                    \
        }                                                                        \
    }

    // ---- main double-buffered pipeline over 16 tiles ----
    for (int t = 0; t < NTILE; t++) {
        if (t < NTILE - 1) asm volatile("cp.async.wait_group 1;");
        else               asm volatile("cp.async.wait_group 0;");
        __syncthreads();

        const int buf  = t & 1;
        const int base = t * TILE;
        if (t == 0) {
            // points 0..31 already consumed by the sort init; do 32..63, then 64..
            {
                const float4 Pa = sp[0][32 + lane];
                const float d0a = fmaf(n0x, Pa.x, fmaf(n0y, Pa.y, fmaf(n0z, Pa.z, Pa.w)));
                const float d1a = fmaf(n1x, Pa.x, fmaf(n1y, Pa.y, fmaf(n1z, Pa.z, Pa.w)));
                const unsigned gate = __ballot_sync(FULLMASK, (d0a < tau0) || (d1a < tau1));
                if (gate) {
                    const int ia = 32 + lane;
                    unsigned ba = __ballot_sync(FULLMASK, d0a < tau0);
                    if (ba) {
                        while (ba) { const int s2 = __ffs(ba) - 1; ba &= ba - 1;
                            ins0(__shfl_sync(FULLMASK, d0a, s2),
                                 __shfl_sync(FULLMASK, ia, s2)); }
                        tau0 = __shfl_sync(FULLMASK, topd, 15);
                    }
                    unsigned be = __ballot_sync(FULLMASK, d1a < tau1);
                    if (be) {
                        while (be) { const int s2 = __ffs(be) - 1; be &= be - 1;
                            ins1(__shfl_sync(FULLMASK, d1a, s2),
                                 __shfl_sync(FULLMASK, ia, s2)); }
                        tau1 = __shfl_sync(FULLMASK, topd, 31);
                    }
                }
            }
            for (int j = 64; j < TILE; j += 64) KNN_CHUNK(0, j, 0)
        } else {
#pragma unroll 4
            for (int j = 0; j < TILE; j += 64) KNN_CHUNK(buf, j, base)
        }
        __syncthreads();
        if (t + 2 < NTILE) ISSUE_TILE(buf, t + 2)
    }
#undef KNN_CHUNK
#undef ISSUE_TILE

    // ---- fused gather/mean for both queries (lists sorted; order irrelevant) ----
    const float* ft = g_xt + (size_t)b * NN * CC;
    float a0 = 0.0f, a1 = 0.0f;   // q0: channels [lane], [lane+32]
    float c0 = 0.0f, c1 = 0.0f;   // q1
#pragma unroll
    for (int r = 0; r < KK; r++) {
        const int gA = __shfl_sync(FULLMASK, topi, r);
        const int gB = __shfl_sync(FULLMASK, topi, 16 + r);
        const float* fA = ft + (size_t)gA * CC;
        const float* fB = ft + (size_t)gB * CC;
        a0 += fA[lane];
        a1 += fA[lane + 32];
        c0 += fB[lane];
        c1 += fB[lane + 32];
    }

    const size_t obase = ((size_t)b * CC + lane) * MM + m0;
    out[obase]                       = a0 * (1.0f / KK);
    out[obase + (size_t)32 * MM]     = a1 * (1.0f / KK);
    out[obase + 1]                   = c0 * (1.0f / KK);
    out[obase + (size_t)32 * MM + 1] = c1 * (1.0f / KK);
}

// ---------------------------------------------------------------------------
extern "C" void kernel_launch(void* const* d_in, const int* in_sizes, int n_in,
                              void* d_out, int out_size) {
    const float* p1 = (const float*)d_in[0];   // (B, N, 3)
    const float* x1 = (const float*)d_in[1];   // (B, C, N)
    const float* p2 = (const float*)d_in[2];   // (B, M, 3)
    float* out = (float*)d_out;                // (B, C, M)

    prep_kernel<<<128 + 2048, 256>>>(p1, x1);

    knn_kernel<<<NP / WPB, TPB>>>(p2, out);
}